// round 2
// baseline (speedup 1.0000x reference)
#include <cuda_runtime.h>
#include <cuda_bf16.h>

// Problem constants
#define BN 1024   // batch
#define TT 512    // seq len
#define EE 64     // embedding
#define H1N 50    // layer-1 hidden
#define G1N 200   // 4*H1
#define HS 52     // padded row stride (floats) for h scratch / smem rows
#define NPAIR 26  // ceil(52/2) j-pairs (j=50,51 zero-padded)

// Scratch (static __device__ globals -- allocation-free per harness rules)
__device__ float g_hf[BN * TT * HS];     // layer1 fwd h, [b][t][j], stride HS
__device__ float g_hb[BN * TT * HS];     // layer1 bwd-dir h at its own step s
__device__ float g_xg1[2 * BN * G1N];    // layer1 input contribution per dir
__device__ float g_xg2f[BN * TT * 4];    // layer2 fwd input gates
__device__ float g_xg2b[BN * TT * 4];    // layer2 bwd input gates
__device__ float g_h2b[BN * TT];         // layer2 bwd output (time-indexed)
__device__ int   g_clf[BN];              // fwd convergence clamp per batch
__device__ int   g_clb[BN];              // bwd convergence clamp per batch

__device__ __forceinline__ float sigx(float x) {
    return __fdividef(1.0f, 1.0f + __expf(-x));
}
__device__ __forceinline__ float tanhx(float x) {
    return __fdividef(2.0f, 1.0f + __expf(-2.0f * x)) - 1.0f;
}

// packed f32x2 helpers (FFMA2 only reachable via PTX fma.rn.f32x2 on sm_103a)
__device__ __forceinline__ unsigned long long pk2(float lo, float hi) {
    unsigned long long r;
    asm("mov.b64 %0, {%1, %2};" : "=l"(r) : "f"(lo), "f"(hi));
    return r;
}
__device__ __forceinline__ float2 upk2(unsigned long long v) {
    float2 r;
    asm("mov.b64 {%0, %1}, %2;" : "=f"(r.x), "=f"(r.y) : "l"(v));
    return r;
}
__device__ __forceinline__ void fma2(unsigned long long& d,
                                     unsigned long long a, unsigned long long b) {
    asm("fma.rn.f32x2 %0, %1, %2, %0;" : "+l"(d) : "l"(a), "l"(b));
}

// ---------------------------------------------------------------------------
// Kernel A: xg1[dir][b][g] = (b_ih+b_hh)[g] + sum_e W_ih[g][e] * x[b][e]
// Input is constant in time -> computed ONCE per (b, dir).
// ---------------------------------------------------------------------------
__global__ void __launch_bounds__(256) xg1_kernel(
    const float* __restrict__ x,
    const float* __restrict__ Wif, const float* __restrict__ bif, const float* __restrict__ bhf,
    const float* __restrict__ Wib, const float* __restrict__ bib, const float* __restrict__ bhb)
{
    __shared__ __align__(16) float sx[EE];
    int b = blockIdx.x;
    int tid = threadIdx.x;
    if (tid < EE) sx[tid] = x[b * EE + tid];
    __syncthreads();

    for (int o = tid; o < 2 * G1N; o += 256) {
        int dir = o / G1N;
        int g = o - dir * G1N;
        const float* W = dir ? Wib : Wif;
        float acc = dir ? (bib[g] + bhb[g]) : (bif[g] + bhf[g]);
        const float4* wr = (const float4*)&W[g * EE];
        #pragma unroll
        for (int e = 0; e < EE / 4; e++) {
            float4 w = wr[e];
            float4 xv = *(const float4*)&sx[4 * e];
            acc += w.x * xv.x + w.y * xv.y + w.z * xv.z + w.w * xv.w;
        }
        g_xg1[dir * BN * G1N + b * G1N + g] = acc;
    }
}

// ---------------------------------------------------------------------------
// Kernel B: layer-1 recurrence. One CTA = 4 batch lanes of one direction.
// Gate thread g (0..199): W_hh row j-pair-packed in 26 x f32x2 registers.
// Per lane, accumulator is f32x2 {accA, accB}; dot product over j runs as
// 26 FFMA2 fed by 13 broadcast LDS.128 from sh_h[lane][j]; cross-half add
// once per step. Halves FMA-pipe occupancy vs scalar FFMA.
// Bitwise fixed-point early exit via __syncthreads_and (doubles as barrier).
// ---------------------------------------------------------------------------
__global__ void __launch_bounds__(256) lstm1_kernel(
    const float* __restrict__ Whhf, const float* __restrict__ Whhb)
{
    int grp = blockIdx.x;      // 0..255  (batch group of 4)
    int dir = blockIdx.y;      // 0..1
    int b0 = grp * 4;
    const float* Whh = dir ? Whhb : Whhf;
    float* hout = dir ? g_hb : g_hf;
    int* clampp = dir ? g_clb : g_clf;

    __shared__ __align__(16) float sh_h[4 * HS];    // [lane][j], stride 52
    __shared__ __align__(16) float sh_g[G1N * 4];   // gates[g][lane]

    int tid = threadIdx.x;
    unsigned long long W2[NPAIR];
    float xg[4];
    if (tid < G1N) {
        #pragma unroll
        for (int p = 0; p < NPAIR; p++) {
            float w0 = (2 * p     < H1N) ? Whh[tid * H1N + 2 * p]     : 0.f;
            float w1 = (2 * p + 1 < H1N) ? Whh[tid * H1N + 2 * p + 1] : 0.f;
            W2[p] = pk2(w0, w1);
        }
        const float* xb = g_xg1 + dir * BN * G1N;
        #pragma unroll
        for (int l = 0; l < 4; l++) xg[l] = xb[(b0 + l) * G1N + tid];
    }
    if (tid < 4 * HS) sh_h[tid] = 0.f;   // includes j=50,51 zero pad

    int uj = tid >> 2;        // hidden unit for update phase
    int ub = tid & 3;         // batch lane for update phase
    float c_st = 0.f, h_st = 0.f;
    bool is_tanh = (tid >= 2 * H1N) && (tid < 3 * H1N);
    __syncthreads();

    int tconv = TT - 1;
    for (int t = 0; t < TT; t++) {
        if (tid < G1N) {
            unsigned long long acc[4];
            #pragma unroll
            for (int l = 0; l < 4; l++) acc[l] = pk2(xg[l], 0.f);
            #pragma unroll
            for (int c = 0; c < HS / 4; c++) {          // 13 chunks of 4 j
                unsigned long long wA = W2[2 * c], wB = W2[2 * c + 1];
                #pragma unroll
                for (int l = 0; l < 4; l++) {
                    ulonglong2 hv = *(const ulonglong2*)&sh_h[l * HS + 4 * c];
                    fma2(acc[l], wA, hv.x);
                    fma2(acc[l], wB, hv.y);
                }
            }
            float a[4];
            #pragma unroll
            for (int l = 0; l < 4; l++) {
                float2 u = upk2(acc[l]);
                a[l] = u.x + u.y;
            }
            if (is_tanh) {
                #pragma unroll
                for (int l = 0; l < 4; l++) a[l] = tanhx(a[l]);
            } else {
                #pragma unroll
                for (int l = 0; l < 4; l++) a[l] = sigx(a[l]);
            }
            *(float4*)&sh_g[tid * 4] = make_float4(a[0], a[1], a[2], a[3]);
        }
        __syncthreads();
        int pred = 1;
        if (tid < G1N) {
            float iv = sh_g[(uj) * 4 + ub];
            float fv = sh_g[(H1N + uj) * 4 + ub];
            float gv = sh_g[(2 * H1N + uj) * 4 + ub];
            float ov = sh_g[(3 * H1N + uj) * 4 + ub];
            float cn = fv * c_st + iv * gv;
            float hn = ov * tanhx(cn);
            pred = (__float_as_int(cn) == __float_as_int(c_st)) &
                   (__float_as_int(hn) == __float_as_int(h_st));
            c_st = cn; h_st = hn;
            sh_h[ub * HS + uj] = hn;
            hout[((b0 + ub) * TT + t) * HS + uj] = hn;
        }
        int conv = __syncthreads_and(pred);
        if (conv) { tconv = t; break; }   // state bitwise-repeated -> exact from here on
    }
    if (tid < 4) clampp[b0 + tid] = tconv;
}

// ---------------------------------------------------------------------------
// Kernel C: layer-2 input gates. One thread per (b, t).
//   h1[b][t] = [hf[b][t], hb_dir[b][511-t]]   (clamped by convergence index)
//   xg2f[b][t]      = b2f + W_ih2f . h1[b][t]
//   xg2b[b][511-t]  = b2b + W_ih2b . h1[b][t]
// ---------------------------------------------------------------------------
__global__ void __launch_bounds__(256) xg2_kernel(
    const float* __restrict__ Wf, const float* __restrict__ Wb,
    const float* __restrict__ bif, const float* __restrict__ bhf,
    const float* __restrict__ bib, const float* __restrict__ bhb)
{
    __shared__ __align__(16) float sWf[4 * 104];
    __shared__ __align__(16) float sWb[4 * 104];
    __shared__ float sbf[4], sbb[4];
    int tid = threadIdx.x;
    for (int i = tid; i < 400; i += 256) {
        int g = i / 100, j = i - g * 100;
        int off = g * 104 + j + (j >= 50 ? 2 : 0);  // hb half padded to 16B align
        sWf[off] = Wf[i];
        sWb[off] = Wb[i];
    }
    if (tid < 4) { sbf[tid] = bif[tid] + bhf[tid]; sbb[tid] = bib[tid] + bhb[tid]; }
    __syncthreads();

    int idx = blockIdx.x * 256 + tid;
    int b = idx >> 9;
    int t = idx & (TT - 1);
    int tc = min(t, g_clf[b]);
    int sc = min(TT - 1 - t, g_clb[b]);
    const float* hfr = &g_hf[(b * TT + tc) * HS];
    const float* hbr = &g_hb[(b * TT + sc) * HS];

    float accf[4], accb[4];
    #pragma unroll
    for (int g = 0; g < 4; g++) { accf[g] = sbf[g]; accb[g] = sbb[g]; }

    // forward-h half (weight cols 0..49)
    #pragma unroll
    for (int k = 0; k < 12; k++) {
        float4 hv = *(const float4*)&hfr[4 * k];
        #pragma unroll
        for (int g = 0; g < 4; g++) {
            float4 wf = *(const float4*)&sWf[g * 104 + 4 * k];
            float4 wb = *(const float4*)&sWb[g * 104 + 4 * k];
            accf[g] += wf.x * hv.x + wf.y * hv.y + wf.z * hv.z + wf.w * hv.w;
            accb[g] += wb.x * hv.x + wb.y * hv.y + wb.z * hv.z + wb.w * hv.w;
        }
    }
    {
        float h48 = hfr[48], h49 = hfr[49];
        #pragma unroll
        for (int g = 0; g < 4; g++) {
            accf[g] += sWf[g * 104 + 48] * h48 + sWf[g * 104 + 49] * h49;
            accb[g] += sWb[g * 104 + 48] * h48 + sWb[g * 104 + 49] * h49;
        }
    }
    // backward-h half (weight cols 50..99, stored at smem offset 52..101)
    #pragma unroll
    for (int k = 0; k < 12; k++) {
        float4 hv = *(const float4*)&hbr[4 * k];
        #pragma unroll
        for (int g = 0; g < 4; g++) {
            float4 wf = *(const float4*)&sWf[g * 104 + 52 + 4 * k];
            float4 wb = *(const float4*)&sWb[g * 104 + 52 + 4 * k];
            accf[g] += wf.x * hv.x + wf.y * hv.y + wf.z * hv.z + wf.w * hv.w;
            accb[g] += wb.x * hv.x + wb.y * hv.y + wb.z * hv.z + wb.w * hv.w;
        }
    }
    {
        float h48 = hbr[48], h49 = hbr[49];
        #pragma unroll
        for (int g = 0; g < 4; g++) {
            accf[g] += sWf[g * 104 + 100] * h48 + sWf[g * 104 + 101] * h49;
            accb[g] += sWb[g * 104 + 100] * h48 + sWb[g * 104 + 101] * h49;
        }
    }

    *(float4*)&g_xg2f[(b * TT + t) * 4] = make_float4(accf[0], accf[1], accf[2], accf[3]);
    *(float4*)&g_xg2b[(b * TT + (TT - 1 - t)) * 4] = make_float4(accb[0], accb[1], accb[2], accb[3]);
}

// ---------------------------------------------------------------------------
// Kernel D: layer-2 recurrence. H2=1 -> scalar state. One thread per (b, dir).
// Fwd writes out[b][t] directly; bwd writes g_h2b[b][t] (summed by kernel E).
// ---------------------------------------------------------------------------
__global__ void __launch_bounds__(256) lstm2_kernel(
    const float* __restrict__ Whhf, const float* __restrict__ Whhb,
    float* __restrict__ out)
{
    int u = blockIdx.x * 256 + threadIdx.x;   // 0..2047
    int b = u & (BN - 1);
    if (u < BN) {
        float w0 = Whhf[0], w1 = Whhf[1], w2 = Whhf[2], w3 = Whhf[3];
        const float4* pre = (const float4*)&g_xg2f[b * TT * 4];
        float h = 0.f, c = 0.f;
        for (int t = 0; t < TT; t++) {
            float4 p = pre[t];
            float iv = sigx(p.x + w0 * h);
            float fv = sigx(p.y + w1 * h);
            float gv = tanhx(p.z + w2 * h);
            float ov = sigx(p.w + w3 * h);
            c = fv * c + iv * gv;
            h = ov * tanhx(c);
            out[b * TT + t] = h;
        }
    } else {
        float w0 = Whhb[0], w1 = Whhb[1], w2 = Whhb[2], w3 = Whhb[3];
        const float4* pre = (const float4*)&g_xg2b[b * TT * 4];
        float h = 0.f, c = 0.f;
        for (int s = 0; s < TT; s++) {
            float4 p = pre[s];
            float iv = sigx(p.x + w0 * h);
            float fv = sigx(p.y + w1 * h);
            float gv = tanhx(p.z + w2 * h);
            float ov = sigx(p.w + w3 * h);
            c = fv * c + iv * gv;
            h = ov * tanhx(c);
            g_h2b[b * TT + (TT - 1 - s)] = h;
        }
    }
}

// ---------------------------------------------------------------------------
// Kernel E: out += h2b (final channel sum)
// ---------------------------------------------------------------------------
__global__ void __launch_bounds__(256) addout_kernel(float* __restrict__ out)
{
    int i = blockIdx.x * 256 + threadIdx.x;   // 0..131071 float4s
    float4* o = (float4*)out;
    const float4* s = (const float4*)g_h2b;
    float4 a = o[i], bv = s[i];
    a.x += bv.x; a.y += bv.y; a.z += bv.z; a.w += bv.w;
    o[i] = a;
}

// ---------------------------------------------------------------------------
extern "C" void kernel_launch(void* const* d_in, const int* in_sizes, int n_in,
                              void* d_out, int out_size)
{
    const float* x    = (const float*)d_in[0];
    const float* Wif1 = (const float*)d_in[1];
    const float* Whf1 = (const float*)d_in[2];
    const float* bif1 = (const float*)d_in[3];
    const float* bhf1 = (const float*)d_in[4];
    const float* Wib1 = (const float*)d_in[5];
    const float* Whb1 = (const float*)d_in[6];
    const float* bib1 = (const float*)d_in[7];
    const float* bhb1 = (const float*)d_in[8];
    const float* Wif2 = (const float*)d_in[9];
    const float* Whf2 = (const float*)d_in[10];
    const float* bif2 = (const float*)d_in[11];
    const float* bhf2 = (const float*)d_in[12];
    const float* Wib2 = (const float*)d_in[13];
    const float* Whb2 = (const float*)d_in[14];
    const float* bib2 = (const float*)d_in[15];
    const float* bhb2 = (const float*)d_in[16];
    float* out = (float*)d_out;

    xg1_kernel<<<BN, 256>>>(x, Wif1, bif1, bhf1, Wib1, bib1, bhb1);
    dim3 gB(BN / 4, 2);
    lstm1_kernel<<<gB, 256>>>(Whf1, Whb1);
    xg2_kernel<<<(BN * TT) / 256, 256>>>(Wif2, Wib2, bif2, bhf2, bib2, bhb2);
    lstm2_kernel<<<8, 256>>>(Whf2, Whb2, out);
    addout_kernel<<<(BN * TT) / 1024, 256>>>(out);
}